// round 1
// baseline (speedup 1.0000x reference)
#include <cuda_runtime.h>
#include <float.h>

// Problem constants
#define BB     2
#define SS     2048
#define DD     2048
#define HH     16
#define HDIM   128
#define WINDOW 256
#define MROWS  (BB * SS)   // 4096

// Scratch (device globals — no allocation allowed)
__device__ float g_q [MROWS * DD];
__device__ float g_k [MROWS * DD];
__device__ float g_v [MROWS * DD];
__device__ float g_ao[MROWS * DD];

// ---------------------------------------------------------------------------
// SGEMM: C[M,N] = A[M,K] @ B[K,N] (+ bias[N] if bias != nullptr)
// 128x128 tile, BK=8, 256 threads, 8x8 per-thread microtile.
// All dims divisible by tile sizes (M=4096, N=K=2048) -> no bounds checks.
// ---------------------------------------------------------------------------
#define BM 128
#define BN 128
#define BKD 8
#define TM 8
#define TN 8

__global__ __launch_bounds__(256) void sgemm_bias_kernel(
    const float* __restrict__ A, const float* __restrict__ B,
    const float* __restrict__ bias, float* __restrict__ C,
    int M, int N, int K)
{
    __shared__ float As[BKD][BM];
    __shared__ float Bs[BKD][BN];

    const int tid   = threadIdx.x;
    const int row0  = blockIdx.y * BM;
    const int col0  = blockIdx.x * BN;

    // A tile loader: 128 rows x 8 cols, one float4 per thread
    const int arow = tid >> 1;
    const int acol = (tid & 1) << 2;
    // B tile loader: 8 rows x 128 cols, one float4 per thread
    const int brw  = tid >> 5;
    const int bcl  = (tid & 31) << 2;
    // compute mapping: 16x16 thread grid, 8x8 microtile
    const int tr   = (tid >> 4) << 3;
    const int tc   = (tid & 15) << 3;

    const float* Ap = A + (long)row0 * K;
    const float* Bp = B + col0;

    float acc[TM][TN];
    #pragma unroll
    for (int i = 0; i < TM; i++)
        #pragma unroll
        for (int j = 0; j < TN; j++)
            acc[i][j] = 0.0f;

    for (int k0 = 0; k0 < K; k0 += BKD) {
        float4 av = *(const float4*)(Ap + (long)arow * K + k0 + acol);
        As[acol + 0][arow] = av.x;
        As[acol + 1][arow] = av.y;
        As[acol + 2][arow] = av.z;
        As[acol + 3][arow] = av.w;
        float4 bv = *(const float4*)(Bp + (long)(k0 + brw) * N + bcl);
        *(float4*)&Bs[brw][bcl] = bv;
        __syncthreads();

        #pragma unroll
        for (int kk = 0; kk < BKD; kk++) {
            float ra[TM], rb[TN];
            *(float4*)&ra[0] = *(const float4*)&As[kk][tr];
            *(float4*)&ra[4] = *(const float4*)&As[kk][tr + 4];
            *(float4*)&rb[0] = *(const float4*)&Bs[kk][tc];
            *(float4*)&rb[4] = *(const float4*)&Bs[kk][tc + 4];
            #pragma unroll
            for (int i = 0; i < TM; i++)
                #pragma unroll
                for (int j = 0; j < TN; j++)
                    acc[i][j] = fmaf(ra[i], rb[j], acc[i][j]);
        }
        __syncthreads();
    }

    #pragma unroll
    for (int i = 0; i < TM; i++) {
        float* Crow = C + (long)(row0 + tr + i) * N + col0 + tc;
        float out[TN];
        #pragma unroll
        for (int j = 0; j < TN; j++) {
            float bb = bias ? bias[col0 + tc + j] : 0.0f;
            out[j] = acc[i][j] + bb;
        }
        *(float4*)(Crow + 0) = *(float4*)&out[0];
        *(float4*)(Crow + 4) = *(float4*)&out[4];
    }
}

// ---------------------------------------------------------------------------
// Local-window attention (flash-style, fp32).
// Grid: (S/BQ, H, B). Block: 256 threads (16x16 grid).
// Each CTA: 64 queries of one (b,h). Keys come in exactly 5 aligned 64-key
// chunks covering [q0-256, q0+63]; negative chunks are skipped entirely.
// Online softmax with masked entries contributing exactly 0 (matches the
// reference where(mask, s, finfo.min) + softmax for all realizable rows).
//
// SMEM layout (floats):
//   Qs[128][65]  (d-major, pad 65 -> conflict-free transpose store + reads)
//   Ks[128][65]
//   Vs[ 64][128]
//   Ps[ 64][64]
// total = 28928 floats = 115712 bytes
// ---------------------------------------------------------------------------
#define BQ   64
#define BKC  64
#define ATT_SMEM_FLOATS (128*65 + 128*65 + 64*128 + 64*64)
#define ATT_SMEM_BYTES  (ATT_SMEM_FLOATS * 4)

__global__ __launch_bounds__(256) void attn_local_kernel(
    const float* __restrict__ Q, const float* __restrict__ K,
    const float* __restrict__ V, const int* __restrict__ amask,
    float* __restrict__ O)
{
    const int q0 = blockIdx.x * BQ;
    const int h  = blockIdx.y;
    const int b  = blockIdx.z;

    extern __shared__ float sm[];
    float* Qs = sm;                       // [128][65]
    float* Ks = Qs + 128 * 65;            // [128][65]
    float* Vs = Ks + 128 * 65;            // [64][128]
    float* Ps = Vs + 64 * 128;            // [64][64]

    const int tid = threadIdx.x;
    const int r   = tid >> 4;             // 0..15 -> rows r*4 .. r*4+3
    const int c   = tid & 15;             // cols c + 16*j (scores), c + 16*dd (output d)

    // Load Q block: global coalesced over d, smem transposed with pad-65
    const float* qbase = Q + ((long)(b * SS + q0)) * DD + h * HDIM;
    for (int e = tid; e < BQ * HDIM; e += 256) {
        int qi = e >> 7, d = e & 127;
        Qs[d * 65 + qi] = qbase[(long)qi * DD + d];
    }

    float m[4], l[4], o[4][8];
    #pragma unroll
    for (int i = 0; i < 4; i++) {
        m[i] = -FLT_MAX; l[i] = 0.0f;
        #pragma unroll
        for (int dd = 0; dd < 8; dd++) o[i][dd] = 0.0f;
    }

    for (int t = 0; t < 5; t++) {
        const int kb = q0 - WINDOW + t * BKC;   // multiple of 64
        if (kb < 0) continue;                    // uniform across CTA

        __syncthreads();  // previous chunk's PV reads done before overwrite

        const float* kbase = K + ((long)(b * SS + kb)) * DD + h * HDIM;
        const float* vbase = V + ((long)(b * SS + kb)) * DD + h * HDIM;
        for (int e = tid; e < BKC * HDIM; e += 256) {
            int kj = e >> 7, d = e & 127;
            float kvf = kbase[(long)kj * DD + d];
            float vvf = vbase[(long)kj * DD + d];
            Ks[d * 65 + kj]  = kvf;
            Vs[kj * 128 + d] = vvf;
        }
        __syncthreads();

        // S = Q @ K^T  (64x64, K-dim 128), unscaled per GPT-Neo quirk
        float s[4][4];
        #pragma unroll
        for (int i = 0; i < 4; i++)
            #pragma unroll
            for (int j = 0; j < 4; j++) s[i][j] = 0.0f;

        for (int d = 0; d < HDIM; d++) {
            float qv[4], kv[4];
            #pragma unroll
            for (int i = 0; i < 4; i++) qv[i] = Qs[d * 65 + r * 4 + i];
            #pragma unroll
            for (int j = 0; j < 4; j++) kv[j] = Ks[d * 65 + c + 16 * j];
            #pragma unroll
            for (int i = 0; i < 4; i++)
                #pragma unroll
                for (int j = 0; j < 4; j++)
                    s[i][j] = fmaf(qv[i], kv[j], s[i][j]);
        }

        // Mask + online softmax update
        float scl[4];
        #pragma unroll
        for (int i = 0; i < 4; i++) {
            const int qi = q0 + r * 4 + i;
            #pragma unroll
            for (int j = 0; j < 4; j++) {
                const int kj = kb + c + 16 * j;
                bool ok = (kj <= qi) && (kj > qi - WINDOW) && (amask[b * SS + kj] > 0);
                if (!ok) s[i][j] = -FLT_MAX;
            }
            float mx = fmaxf(fmaxf(s[i][0], s[i][1]), fmaxf(s[i][2], s[i][3]));
            #pragma unroll
            for (int w = 1; w <= 8; w <<= 1)
                mx = fmaxf(mx, __shfl_xor_sync(0xffffffffu, mx, w));

            float mnew = fmaxf(m[i], mx);
            scl[i] = __expf(m[i] - mnew);
            m[i] = mnew;

            float sum = 0.0f;
            #pragma unroll
            for (int j = 0; j < 4; j++) {
                float p = (s[i][j] > -1e37f) ? __expf(s[i][j] - mnew) : 0.0f;
                s[i][j] = p;
                sum += p;
            }
            #pragma unroll
            for (int w = 1; w <= 8; w <<= 1)
                sum += __shfl_xor_sync(0xffffffffu, sum, w);

            l[i] = l[i] * scl[i] + sum;
            #pragma unroll
            for (int dd = 0; dd < 8; dd++) o[i][dd] *= scl[i];
        }

        // Stage P (probabilities) to shared for PV gemm
        #pragma unroll
        for (int i = 0; i < 4; i++)
            #pragma unroll
            for (int j = 0; j < 4; j++)
                Ps[(r * 4 + i) * 64 + c + 16 * j] = s[i][j];
        __syncthreads();

        // O += P @ V   (64x128, inner 64)
        #pragma unroll 4
        for (int j = 0; j < BKC; j++) {
            float pv[4];
            #pragma unroll
            for (int i = 0; i < 4; i++) pv[i] = Ps[(r * 4 + i) * 64 + j];
            #pragma unroll
            for (int dd = 0; dd < 8; dd++) {
                float vv = Vs[j * 128 + c + 16 * dd];
                #pragma unroll
                for (int i = 0; i < 4; i++)
                    o[i][dd] = fmaf(pv[i], vv, o[i][dd]);
            }
        }
    }

    // Normalize + store
    #pragma unroll
    for (int i = 0; i < 4; i++) {
        const int row = q0 + r * 4 + i;
        const float inv = 1.0f / l[i];
        float* obase = O + ((long)(b * SS + row)) * DD + h * HDIM;
        #pragma unroll
        for (int dd = 0; dd < 8; dd++)
            obase[c + 16 * dd] = o[i][dd] * inv;
    }
}

// ---------------------------------------------------------------------------
// Launch
// ---------------------------------------------------------------------------
extern "C" void kernel_launch(void* const* d_in, const int* in_sizes, int n_in,
                              void* d_out, int out_size)
{
    const float* hs    = (const float*)d_in[0];
    const int*   amask = (const int*)  d_in[1];
    const float* Wq    = (const float*)d_in[2];
    const float* Wk    = (const float*)d_in[3];
    const float* Wv    = (const float*)d_in[4];
    const float* Wo    = (const float*)d_in[5];
    const float* bo    = (const float*)d_in[6];
    float*       out   = (float*)d_out;

    float *q, *k, *v, *ao;
    cudaGetSymbolAddress((void**)&q,  g_q);
    cudaGetSymbolAddress((void**)&k,  g_k);
    cudaGetSymbolAddress((void**)&v,  g_v);
    cudaGetSymbolAddress((void**)&ao, g_ao);

    dim3 gemm_grid(DD / BN, MROWS / BM);   // (16, 32)

    sgemm_bias_kernel<<<gemm_grid, 256>>>(hs, Wq, nullptr, q, MROWS, DD, DD);
    sgemm_bias_kernel<<<gemm_grid, 256>>>(hs, Wk, nullptr, k, MROWS, DD, DD);
    sgemm_bias_kernel<<<gemm_grid, 256>>>(hs, Wv, nullptr, v, MROWS, DD, DD);

    cudaFuncSetAttribute(attn_local_kernel,
                         cudaFuncAttributeMaxDynamicSharedMemorySize,
                         ATT_SMEM_BYTES);
    dim3 attn_grid(SS / BQ, HH, BB);       // (32, 16, 2)
    attn_local_kernel<<<attn_grid, 256, ATT_SMEM_BYTES>>>(q, k, v, amask, ao);

    sgemm_bias_kernel<<<gemm_grid, 256>>>(ao, Wo, bo, out, MROWS, DD, DD);
}

// round 3
// speedup vs baseline: 1.8579x; 1.8579x over previous
#include <cuda_runtime.h>
#include <cuda_bf16.h>
#include <float.h>
#include <stdint.h>

// Problem constants
#define BB     2
#define SS     2048
#define DD     2048
#define HH     16
#define HDIM   128
#define WINDOW 256
#define MROWS  (BB * SS)   // 4096

// ---------------------------------------------------------------------------
// Scratch (device globals — no allocation allowed)
// ---------------------------------------------------------------------------
__device__ float g_q [MROWS * DD];
__device__ float g_k [MROWS * DD];
__device__ float g_v [MROWS * DD];
__device__ float g_ao[MROWS * DD];
__device__ __nv_bfloat16 g_ahi[MROWS * DD];
__device__ __nv_bfloat16 g_alo[MROWS * DD];
__device__ __nv_bfloat16 g_whi[DD * DD];
__device__ __nv_bfloat16 g_wlo[DD * DD];

// ---------------------------------------------------------------------------
// PTX helpers (family-wide instructions only — harness targets compute_103,
// so NO tcgen05/TMEM; mma.sync + ldmatrix + cp.async are safe)
// ---------------------------------------------------------------------------
__device__ __forceinline__ uint32_t smem_u32(const void* p) {
    uint32_t a;
    asm("{ .reg .u64 t; cvta.to.shared.u64 t, %1; cvt.u32.u64 %0, t; }"
        : "=r"(a) : "l"(p));
    return a;
}

#define CP16(dst, src) \
    asm volatile("cp.async.cg.shared.global [%0], [%1], 16;" :: "r"(dst), "l"(src))
#define CP_COMMIT() asm volatile("cp.async.commit_group;" ::: "memory")
#define CP_WAIT2()  asm volatile("cp.async.wait_group 2;" ::: "memory")

#define LDSM_X4(r0, r1, r2, r3, addr) \
    asm volatile("ldmatrix.sync.aligned.m8n8.x4.shared.b16 {%0,%1,%2,%3}, [%4];" \
        : "=r"(r0), "=r"(r1), "=r"(r2), "=r"(r3) : "r"(addr))

#define MMA16816(d, a, b) \
    asm volatile("mma.sync.aligned.m16n8k16.row.col.f32.bf16.bf16.f32 " \
        "{%0,%1,%2,%3}, {%4,%5,%6,%7}, {%8,%9}, {%0,%1,%2,%3};" \
        : "+f"((d)[0]), "+f"((d)[1]), "+f"((d)[2]), "+f"((d)[3]) \
        : "r"((a)[0]), "r"((a)[1]), "r"((a)[2]), "r"((a)[3]), \
          "r"((b)[0]), "r"((b)[1]))

// ---------------------------------------------------------------------------
// Split fp32 -> bf16 hi + lo (grid-stride over float4)
// ---------------------------------------------------------------------------
__global__ __launch_bounds__(256) void split_kernel(
    const float* __restrict__ X, __nv_bfloat16* __restrict__ H,
    __nv_bfloat16* __restrict__ L, int n4)
{
    int i = blockIdx.x * blockDim.x + threadIdx.x;
    if (i >= n4) return;
    float4 x = ((const float4*)X)[i];
    __nv_bfloat16 h0 = __float2bfloat16(x.x);
    __nv_bfloat16 h1 = __float2bfloat16(x.y);
    __nv_bfloat16 h2 = __float2bfloat16(x.z);
    __nv_bfloat16 h3 = __float2bfloat16(x.w);
    __nv_bfloat16 l0 = __float2bfloat16(x.x - __bfloat162float(h0));
    __nv_bfloat16 l1 = __float2bfloat16(x.y - __bfloat162float(h1));
    __nv_bfloat16 l2 = __float2bfloat16(x.z - __bfloat162float(h2));
    __nv_bfloat16 l3 = __float2bfloat16(x.w - __bfloat162float(h3));
    ((__nv_bfloat162*)H)[2*i]   = __nv_bfloat162(h0, h1);
    ((__nv_bfloat162*)H)[2*i+1] = __nv_bfloat162(h2, h3);
    ((__nv_bfloat162*)L)[2*i]   = __nv_bfloat162(l0, l1);
    ((__nv_bfloat162*)L)[2*i+1] = __nv_bfloat162(l2, l3);
}

// ---------------------------------------------------------------------------
// W [K][N] fp32 -> transposed + split: TH/TL [N][K] bf16
// ---------------------------------------------------------------------------
__global__ __launch_bounds__(256) void wsplitT_kernel(
    const float* __restrict__ W, __nv_bfloat16* __restrict__ TH,
    __nv_bfloat16* __restrict__ TL)
{
    __shared__ float t[32][33];
    const int n0 = blockIdx.x * 32, k0 = blockIdx.y * 32;
    const int tx = threadIdx.x & 31, ty = threadIdx.x >> 5;  // ty 0..7
    #pragma unroll
    for (int i = 0; i < 32; i += 8)
        t[ty + i][tx] = W[(long)(k0 + ty + i) * DD + n0 + tx];
    __syncthreads();
    #pragma unroll
    for (int i = 0; i < 32; i += 8) {
        float x = t[tx][ty + i];             // = W[k0+tx][n0+ty+i]
        long o = (long)(n0 + ty + i) * DD + k0 + tx;
        __nv_bfloat16 h = __float2bfloat16(x);
        TH[o] = h;
        TL[o] = __float2bfloat16(x - __bfloat162float(h));
    }
}

// ---------------------------------------------------------------------------
// bf16x3 HMMA GEMM: C[4096,2048] = A @ Bt^T   (Bt is [N][K] row-major)
// C = Ahi@Bhi + Ahi@Blo + Alo@Bhi, fp32 register accumulation.
// CTA: 128x128 tile, 256 threads (8 warps, each 32x64), BK=64, 4-stage cp.async.
// SMEM per stage: A[128][64] + B[128][64] bf16, rows padded to 72 elems (144B).
// ---------------------------------------------------------------------------
#define GKB      64
#define GNIT     96                       // 3 passes * 32 k-blocks
#define GSTAGES  4
#define GPAD     72                       // row stride in bf16 elems (144B)
#define G_OPB    (128 * GPAD * 2)         // 18432 B per operand
#define G_STAGEB (2 * G_OPB)              // 36864 B
#define GSMEM_TOTAL (GSTAGES * G_STAGEB)  // 147456 B

__device__ __forceinline__ void g_load_stage(
    uint32_t sbase, int stage, int tid,
    const __nv_bfloat16* __restrict__ Asrc, const __nv_bfloat16* __restrict__ Bsrc,
    long row0, long col0, int kc)
{
    const uint32_t abase = sbase + stage * G_STAGEB;
    const uint32_t bbase = abase + G_OPB;
    const __nv_bfloat16* Ap = Asrc + row0 * DD + kc;
    const __nv_bfloat16* Bp = Bsrc + col0 * DD + kc;
    #pragma unroll
    for (int i = 0; i < 4; i++) {
        int idx = i * 256 + tid;
        int r  = idx >> 3;                 // 0..127
        int ch = idx & 7;                  // 16B chunk within 128B of row data
        uint32_t so = (uint32_t)(r * (GPAD * 2) + ch * 16);
        CP16(abase + so, Ap + (long)r * DD + ch * 8);
        CP16(bbase + so, Bp + (long)r * DD + ch * 8);
    }
}

__global__ __launch_bounds__(256, 1) void gemm_bf16x3_kernel(
    const __nv_bfloat16* __restrict__ Ahi, const __nv_bfloat16* __restrict__ Alo,
    const __nv_bfloat16* __restrict__ Bhi, const __nv_bfloat16* __restrict__ Blo,
    const float* __restrict__ bias, float* __restrict__ C)
{
    extern __shared__ char gsm[];
    const uint32_t sb = smem_u32(gsm);
    const int tid  = threadIdx.x;
    const int wid  = tid >> 5;
    const int lane = tid & 31;
    const long col0 = (long)blockIdx.x * 128;
    const long row0 = (long)blockIdx.y * 128;

    const int warp_m = (wid >> 1) * 32;    // 0,32,64,96
    const int warp_n = (wid & 1) * 64;     // 0,64
    const int lr = lane & 15;              // ldmatrix row-within-16
    const int hl = lane >> 4;              // ldmatrix k-half select

    float acc[2][8][4];
    #pragma unroll
    for (int mt = 0; mt < 2; mt++)
        #pragma unroll
        for (int nt = 0; nt < 8; nt++)
            #pragma unroll
            for (int e = 0; e < 4; e++)
                acc[mt][nt][e] = 0.0f;

    // Prologue: stages 0..2, all pass 0 (Ahi*Bhi)
    #pragma unroll 1
    for (int s = 0; s < GSTAGES - 1; s++) {
        g_load_stage(sb, s, tid, Ahi, Bhi, row0, col0, s * GKB);
        CP_COMMIT();
    }

    #pragma unroll 1
    for (int it = 0; it < GNIT; it++) {
        const int s = it & (GSTAGES - 1);
        CP_WAIT2();
        __syncthreads();

        // Prefetch stage it+3
        const int nit = it + 3;
        if (nit < GNIT) {
            const int pass = nit >> 5;
            const int kc = (nit & 31) * GKB;
            const __nv_bfloat16* As = (pass == 2) ? Alo : Ahi;
            const __nv_bfloat16* Bs = (pass == 1) ? Blo : Bhi;
            g_load_stage(sb, nit & (GSTAGES - 1), tid, As, Bs, row0, col0, kc);
        }
        CP_COMMIT();

        // Compute on stage s
        const uint32_t sA = sb + s * G_STAGEB;
        const uint32_t sB = sA + G_OPB;
        #pragma unroll
        for (int ks = 0; ks < 4; ks++) {
            const int k0 = ks * 16;
            uint32_t aF[2][4], bF[8][2];
            #pragma unroll
            for (int mt = 0; mt < 2; mt++) {
                uint32_t addr = sA + (uint32_t)((warp_m + mt * 16 + lr) * (GPAD * 2)
                                              + (k0 + 8 * hl) * 2);
                LDSM_X4(aF[mt][0], aF[mt][1], aF[mt][2], aF[mt][3], addr);
            }
            #pragma unroll
            for (int nt2 = 0; nt2 < 4; nt2++) {
                uint32_t r0, r1, r2, r3;
                uint32_t addr = sB + (uint32_t)((warp_n + nt2 * 16 + lr) * (GPAD * 2)
                                              + (k0 + 8 * hl) * 2);
                LDSM_X4(r0, r1, r2, r3, addr);
                bF[2 * nt2][0]     = r0;  // n-tile even: b0
                bF[2 * nt2 + 1][0] = r1;  // n-tile odd:  b0
                bF[2 * nt2][1]     = r2;  // even: b1
                bF[2 * nt2 + 1][1] = r3;  // odd:  b1
            }
            #pragma unroll
            for (int mt = 0; mt < 2; mt++)
                #pragma unroll
                for (int nt = 0; nt < 8; nt++)
                    MMA16816(acc[mt][nt], aF[mt], bF[nt]);
        }
    }

    // Epilogue: write fp32 (+bias). Acc layout per m16n8 tile:
    //   d0,d1 -> (row=lane/4,     col=(lane%4)*2, +1)
    //   d2,d3 -> (row=lane/4 + 8, same cols)
    const int erow = lane >> 2;
    const int ecol = (lane & 3) * 2;
    #pragma unroll
    for (int mt = 0; mt < 2; mt++) {
        #pragma unroll
        for (int nt = 0; nt < 8; nt++) {
            const long r  = row0 + warp_m + mt * 16 + erow;
            const long cc = col0 + warp_n + nt * 8 + ecol;
            float b0 = bias ? bias[cc] : 0.0f;
            float b1 = bias ? bias[cc + 1] : 0.0f;
            float2 v0 = make_float2(acc[mt][nt][0] + b0, acc[mt][nt][1] + b1);
            float2 v1 = make_float2(acc[mt][nt][2] + b0, acc[mt][nt][3] + b1);
            *(float2*)(C + r * DD + cc)       = v0;
            *(float2*)(C + (r + 8) * DD + cc) = v1;
        }
    }
}

// ---------------------------------------------------------------------------
// Local-window attention (flash-style, fp32) — unchanged from round 1
// ---------------------------------------------------------------------------
#define BQ   64
#define BKC  64
#define ATT_SMEM_FLOATS (128*65 + 128*65 + 64*128 + 64*64)
#define ATT_SMEM_BYTES  (ATT_SMEM_FLOATS * 4)

__global__ __launch_bounds__(256) void attn_local_kernel(
    const float* __restrict__ Q, const float* __restrict__ K,
    const float* __restrict__ V, const int* __restrict__ amask,
    float* __restrict__ O)
{
    const int q0 = blockIdx.x * BQ;
    const int h  = blockIdx.y;
    const int b  = blockIdx.z;

    extern __shared__ float sm[];
    float* Qs = sm;
    float* Ks = Qs + 128 * 65;
    float* Vs = Ks + 128 * 65;
    float* Ps = Vs + 64 * 128;

    const int tid = threadIdx.x;
    const int r   = tid >> 4;
    const int c   = tid & 15;

    const float* qbase = Q + ((long)(b * SS + q0)) * DD + h * HDIM;
    for (int e = tid; e < BQ * HDIM; e += 256) {
        int qi = e >> 7, d = e & 127;
        Qs[d * 65 + qi] = qbase[(long)qi * DD + d];
    }

    float m[4], l[4], o[4][8];
    #pragma unroll
    for (int i = 0; i < 4; i++) {
        m[i] = -FLT_MAX; l[i] = 0.0f;
        #pragma unroll
        for (int dd = 0; dd < 8; dd++) o[i][dd] = 0.0f;
    }

    for (int t = 0; t < 5; t++) {
        const int kb = q0 - WINDOW + t * BKC;
        if (kb < 0) continue;

        __syncthreads();

        const float* kbase = K + ((long)(b * SS + kb)) * DD + h * HDIM;
        const float* vbase = V + ((long)(b * SS + kb)) * DD + h * HDIM;
        for (int e = tid; e < BKC * HDIM; e += 256) {
            int kj = e >> 7, d = e & 127;
            Ks[d * 65 + kj]  = kbase[(long)kj * DD + d];
            Vs[kj * 128 + d] = vbase[(long)kj * DD + d];
        }
        __syncthreads();

        float s[4][4];
        #pragma unroll
        for (int i = 0; i < 4; i++)
            #pragma unroll
            for (int j = 0; j < 4; j++) s[i][j] = 0.0f;

        for (int d = 0; d < HDIM; d++) {
            float qv[4], kv[4];
            #pragma unroll
            for (int i = 0; i < 4; i++) qv[i] = Qs[d * 65 + r * 4 + i];
            #pragma unroll
            for (int j = 0; j < 4; j++) kv[j] = Ks[d * 65 + c + 16 * j];
            #pragma unroll
            for (int i = 0; i < 4; i++)
                #pragma unroll
                for (int j = 0; j < 4; j++)
                    s[i][j] = fmaf(qv[i], kv[j], s[i][j]);
        }

        float scl[4];
        #pragma unroll
        for (int i = 0; i < 4; i++) {
            const int qi = q0 + r * 4 + i;
            #pragma unroll
            for (int j = 0; j < 4; j++) {
                const int kj = kb + c + 16 * j;
                bool ok = (kj <= qi) && (kj > qi - WINDOW) && (amask[b * SS + kj] > 0);
                if (!ok) s[i][j] = -FLT_MAX;
            }
            float mx = fmaxf(fmaxf(s[i][0], s[i][1]), fmaxf(s[i][2], s[i][3]));
            #pragma unroll
            for (int w = 1; w <= 8; w <<= 1)
                mx = fmaxf(mx, __shfl_xor_sync(0xffffffffu, mx, w));

            float mnew = fmaxf(m[i], mx);
            scl[i] = __expf(m[i] - mnew);
            m[i] = mnew;

            float sum = 0.0f;
            #pragma unroll
            for (int j = 0; j < 4; j++) {
                float p = (s[i][j] > -1e37f) ? __expf(s[i][j] - mnew) : 0.0f;
                s[i][j] = p;
                sum += p;
            }
            #pragma unroll
            for (int w = 1; w <= 8; w <<= 1)
                sum += __shfl_xor_sync(0xffffffffu, sum, w);

            l[i] = l[i] * scl[i] + sum;
            #pragma unroll
            for (int dd = 0; dd < 8; dd++) o[i][dd] *= scl[i];
        }

        #pragma unroll
        for (int i = 0; i < 4; i++)
            #pragma unroll
            for (int j = 0; j < 4; j++)
                Ps[(r * 4 + i) * 64 + c + 16 * j] = s[i][j];
        __syncthreads();

        #pragma unroll 4
        for (int j = 0; j < BKC; j++) {
            float pv[4];
            #pragma unroll
            for (int i = 0; i < 4; i++) pv[i] = Ps[(r * 4 + i) * 64 + j];
            #pragma unroll
            for (int dd = 0; dd < 8; dd++) {
                float vv = Vs[j * 128 + c + 16 * dd];
                #pragma unroll
                for (int i = 0; i < 4; i++)
                    o[i][dd] = fmaf(pv[i], vv, o[i][dd]);
            }
        }
    }

    #pragma unroll
    for (int i = 0; i < 4; i++) {
        const int row = q0 + r * 4 + i;
        const float inv = 1.0f / l[i];
        float* obase = O + ((long)(b * SS + row)) * DD + h * HDIM;
        #pragma unroll
        for (int dd = 0; dd < 8; dd++)
            obase[c + 16 * dd] = o[i][dd] * inv;
    }
}

// ---------------------------------------------------------------------------
// Launch
// ---------------------------------------------------------------------------
extern "C" void kernel_launch(void* const* d_in, const int* in_sizes, int n_in,
                              void* d_out, int out_size)
{
    const float* hs    = (const float*)d_in[0];
    const int*   amask = (const int*)  d_in[1];
    const float* Wq    = (const float*)d_in[2];
    const float* Wk    = (const float*)d_in[3];
    const float* Wv    = (const float*)d_in[4];
    const float* Wo    = (const float*)d_in[5];
    const float* bo    = (const float*)d_in[6];
    float*       out   = (float*)d_out;

    float *q, *k, *v, *ao;
    __nv_bfloat16 *ahi, *alo, *whi, *wlo;
    cudaGetSymbolAddress((void**)&q,   g_q);
    cudaGetSymbolAddress((void**)&k,   g_k);
    cudaGetSymbolAddress((void**)&v,   g_v);
    cudaGetSymbolAddress((void**)&ao,  g_ao);
    cudaGetSymbolAddress((void**)&ahi, g_ahi);
    cudaGetSymbolAddress((void**)&alo, g_alo);
    cudaGetSymbolAddress((void**)&whi, g_whi);
    cudaGetSymbolAddress((void**)&wlo, g_wlo);

    cudaFuncSetAttribute(gemm_bf16x3_kernel,
                         cudaFuncAttributeMaxDynamicSharedMemorySize, GSMEM_TOTAL);
    cudaFuncSetAttribute(attn_local_kernel,
                         cudaFuncAttributeMaxDynamicSharedMemorySize, ATT_SMEM_BYTES);

    const int n4 = MROWS * DD / 4;
    dim3 wgrid(DD / 32, DD / 32);          // (64, 64)
    dim3 ggrid(DD / 128, MROWS / 128);     // (16, 32)

    split_kernel<<<(n4 + 255) / 256, 256>>>(hs, ahi, alo, n4);

    wsplitT_kernel<<<wgrid, 256>>>(Wq, whi, wlo);
    gemm_bf16x3_kernel<<<ggrid, 256, GSMEM_TOTAL>>>(ahi, alo, whi, wlo, nullptr, q);

    wsplitT_kernel<<<wgrid, 256>>>(Wk, whi, wlo);
    gemm_bf16x3_kernel<<<ggrid, 256, GSMEM_TOTAL>>>(ahi, alo, whi, wlo, nullptr, k);

    wsplitT_kernel<<<wgrid, 256>>>(Wv, whi, wlo);
    gemm_bf16x3_kernel<<<ggrid, 256, GSMEM_TOTAL>>>(ahi, alo, whi, wlo, nullptr, v);

    dim3 attn_grid(SS / BQ, HH, BB);       // (32, 16, 2)
    attn_local_kernel<<<attn_grid, 256, ATT_SMEM_BYTES>>>(q, k, v, amask, ao);

    split_kernel<<<(n4 + 255) / 256, 256>>>(ao, ahi, alo, n4);
    wsplitT_kernel<<<wgrid, 256>>>(Wo, whi, wlo);
    gemm_bf16x3_kernel<<<ggrid, 256, GSMEM_TOTAL>>>(ahi, alo, whi, wlo, bo, out);
}

// round 4
// speedup vs baseline: 2.1342x; 1.1487x over previous
#include <cuda_runtime.h>
#include <cuda_bf16.h>
#include <float.h>
#include <stdint.h>

// Problem constants
#define BB     2
#define SS     2048
#define DD     2048
#define HH     16
#define HDIM   128
#define WINDOW 256
#define MROWS  (BB * SS)   // 4096
#define MD     ((long)MROWS * DD)

// ---------------------------------------------------------------------------
// Scratch (device globals — no allocation allowed)
// ---------------------------------------------------------------------------
__device__ float g_qkv[3 * MROWS * DD];     // q | k | v
__device__ float g_ao [MROWS * DD];
__device__ __nv_bfloat16 g_ahi[MROWS * DD];
__device__ __nv_bfloat16 g_alo[MROWS * DD];
__device__ __nv_bfloat16 g_whi[3 * DD * DD];  // packed Wq|Wk|Wv (then slot0 reused for Wo)
__device__ __nv_bfloat16 g_wlo[3 * DD * DD];

// ---------------------------------------------------------------------------
// PTX helpers (family-wide only: harness emits compute_103 PTX -> no tcgen05)
// ---------------------------------------------------------------------------
__device__ __forceinline__ uint32_t smem_u32(const void* p) {
    uint32_t a;
    asm("{ .reg .u64 t; cvta.to.shared.u64 t, %1; cvt.u32.u64 %0, t; }"
        : "=r"(a) : "l"(p));
    return a;
}

#define CP16(dst, src) \
    asm volatile("cp.async.cg.shared.global [%0], [%1], 16;" :: "r"(dst), "l"(src))
#define CP_COMMIT() asm volatile("cp.async.commit_group;" ::: "memory")
#define CP_WAIT1()  asm volatile("cp.async.wait_group 1;" ::: "memory")

#define LDSM_X4(r0, r1, r2, r3, addr) \
    asm volatile("ldmatrix.sync.aligned.m8n8.x4.shared.b16 {%0,%1,%2,%3}, [%4];" \
        : "=r"(r0), "=r"(r1), "=r"(r2), "=r"(r3) : "r"(addr))

#define MMA16816(d, a, b) \
    asm volatile("mma.sync.aligned.m16n8k16.row.col.f32.bf16.bf16.f32 " \
        "{%0,%1,%2,%3}, {%4,%5,%6,%7}, {%8,%9}, {%0,%1,%2,%3};" \
        : "+f"((d)[0]), "+f"((d)[1]), "+f"((d)[2]), "+f"((d)[3]) \
        : "r"((a)[0]), "r"((a)[1]), "r"((a)[2]), "r"((a)[3]), \
          "r"((b)[0]), "r"((b)[1]))

// ---------------------------------------------------------------------------
// Split fp32 -> bf16 hi + lo (grid-stride over float4)
// ---------------------------------------------------------------------------
__global__ __launch_bounds__(256) void split_kernel(
    const float* __restrict__ X, __nv_bfloat16* __restrict__ H,
    __nv_bfloat16* __restrict__ L, int n4)
{
    int i = blockIdx.x * blockDim.x + threadIdx.x;
    if (i >= n4) return;
    float4 x = ((const float4*)X)[i];
    __nv_bfloat16 h0 = __float2bfloat16(x.x);
    __nv_bfloat16 h1 = __float2bfloat16(x.y);
    __nv_bfloat16 h2 = __float2bfloat16(x.z);
    __nv_bfloat16 h3 = __float2bfloat16(x.w);
    __nv_bfloat16 l0 = __float2bfloat16(x.x - __bfloat162float(h0));
    __nv_bfloat16 l1 = __float2bfloat16(x.y - __bfloat162float(h1));
    __nv_bfloat16 l2 = __float2bfloat16(x.z - __bfloat162float(h2));
    __nv_bfloat16 l3 = __float2bfloat16(x.w - __bfloat162float(h3));
    ((__nv_bfloat162*)H)[2*i]   = __nv_bfloat162(h0, h1);
    ((__nv_bfloat162*)H)[2*i+1] = __nv_bfloat162(h2, h3);
    ((__nv_bfloat162*)L)[2*i]   = __nv_bfloat162(l0, l1);
    ((__nv_bfloat162*)L)[2*i+1] = __nv_bfloat162(l2, l3);
}

// ---------------------------------------------------------------------------
// W [K][N] fp32 -> transposed + split: TH/TL [N][K] bf16
// ---------------------------------------------------------------------------
__global__ __launch_bounds__(256) void wsplitT_kernel(
    const float* __restrict__ W, __nv_bfloat16* __restrict__ TH,
    __nv_bfloat16* __restrict__ TL)
{
    __shared__ float t[32][33];
    const int n0 = blockIdx.x * 32, k0 = blockIdx.y * 32;
    const int tx = threadIdx.x & 31, ty = threadIdx.x >> 5;  // ty 0..7
    #pragma unroll
    for (int i = 0; i < 32; i += 8)
        t[ty + i][tx] = W[(long)(k0 + ty + i) * DD + n0 + tx];
    __syncthreads();
    #pragma unroll
    for (int i = 0; i < 32; i += 8) {
        float x = t[tx][ty + i];             // = W[k0+tx][n0+ty+i]
        long o = (long)(n0 + ty + i) * DD + k0 + tx;
        __nv_bfloat16 h = __float2bfloat16(x);
        TH[o] = h;
        TL[o] = __float2bfloat16(x - __bfloat162float(h));
    }
}

// ---------------------------------------------------------------------------
// bf16x3 HMMA GEMM with packed-N weights.
// C[which][4096, 2048] = A @ BtPacked[which]^T, which = (bx*128)/2048.
// 3-stage cp.async ring, 2 CTAs/SM. 256 threads, warp tile 32x64.
// ---------------------------------------------------------------------------
#define GKB      64
#define GNIT     96                       // 3 passes * 32 k-blocks
#define GPAD     72                       // row stride in bf16 elems (144B)
#define G_OPB    (128 * GPAD * 2)         // 18432 B per operand
#define G_STAGEB (2 * G_OPB)              // 36864 B
#define GSMEM_TOTAL (3 * G_STAGEB)        // 110592 B

__device__ __forceinline__ void g_load_stage(
    uint32_t sbase, int stage, int tid,
    const __nv_bfloat16* __restrict__ Asrc, const __nv_bfloat16* __restrict__ Bsrc,
    long row0, long bcol0, int kc)
{
    const uint32_t abase = sbase + stage * G_STAGEB;
    const uint32_t bbase = abase + G_OPB;
    const __nv_bfloat16* Ap = Asrc + row0 * DD + kc;
    const __nv_bfloat16* Bp = Bsrc + bcol0 * DD + kc;
    #pragma unroll
    for (int i = 0; i < 4; i++) {
        int idx = i * 256 + tid;
        int r  = idx >> 3;                 // 0..127
        int ch = idx & 7;                  // 16B chunk within 128B of row data
        uint32_t so = (uint32_t)(r * (GPAD * 2) + ch * 16);
        CP16(abase + so, Ap + (long)r * DD + ch * 8);
        CP16(bbase + so, Bp + (long)r * DD + ch * 8);
    }
}

__global__ __launch_bounds__(256, 2) void gemm_bf16x3_kernel(
    const __nv_bfloat16* __restrict__ Ahi, const __nv_bfloat16* __restrict__ Alo,
    const __nv_bfloat16* __restrict__ Bhi, const __nv_bfloat16* __restrict__ Blo,
    const float* __restrict__ bias, float* __restrict__ Cbase)
{
    extern __shared__ char gsm[];
    const uint32_t sb = smem_u32(gsm);
    const int tid  = threadIdx.x;
    const int wid  = tid >> 5;
    const int lane = tid & 31;
    const long bcol0 = (long)blockIdx.x * 128;       // packed-weight row offset
    const long row0  = (long)blockIdx.y * 128;
    const int  which = (int)(bcol0 >> 11);           // 0..2
    const long cc0   = bcol0 & 2047;                 // column within output
    float* C = Cbase + (long)which * MD;

    const int warp_m = (wid >> 1) * 32;
    const int warp_n = (wid & 1) * 64;
    const int lr = lane & 15;
    const int hl = lane >> 4;

    float acc[2][8][4];
    #pragma unroll
    for (int mt = 0; mt < 2; mt++)
        #pragma unroll
        for (int nt = 0; nt < 8; nt++)
            #pragma unroll
            for (int e = 0; e < 4; e++)
                acc[mt][nt][e] = 0.0f;

    // Prologue: stages 0,1 (pass 0: Ahi*Bhi)
    g_load_stage(sb, 0, tid, Ahi, Bhi, row0, bcol0, 0);
    CP_COMMIT();
    g_load_stage(sb, 1, tid, Ahi, Bhi, row0, bcol0, GKB);
    CP_COMMIT();

    int s = 0, ps = 2;
    #pragma unroll 1
    for (int it = 0; it < GNIT; it++) {
        CP_WAIT1();
        __syncthreads();

        // Prefetch stage it+2
        const int nit = it + 2;
        if (nit < GNIT) {
            const int pass = nit >> 5;
            const int kc = (nit & 31) * GKB;
            const __nv_bfloat16* As = (pass == 2) ? Alo : Ahi;
            const __nv_bfloat16* Bs = (pass == 1) ? Blo : Bhi;
            g_load_stage(sb, ps, tid, As, Bs, row0, bcol0, kc);
        }
        CP_COMMIT();

        // Compute on stage s
        const uint32_t sA = sb + s * G_STAGEB;
        const uint32_t sB = sA + G_OPB;
        #pragma unroll
        for (int ks = 0; ks < 4; ks++) {
            const int k0 = ks * 16;
            uint32_t aF[2][4], bF[8][2];
            #pragma unroll
            for (int mt = 0; mt < 2; mt++) {
                uint32_t addr = sA + (uint32_t)((warp_m + mt * 16 + lr) * (GPAD * 2)
                                              + (k0 + 8 * hl) * 2);
                LDSM_X4(aF[mt][0], aF[mt][1], aF[mt][2], aF[mt][3], addr);
            }
            #pragma unroll
            for (int nt2 = 0; nt2 < 4; nt2++) {
                uint32_t r0, r1, r2, r3;
                uint32_t addr = sB + (uint32_t)((warp_n + nt2 * 16 + lr) * (GPAD * 2)
                                              + (k0 + 8 * hl) * 2);
                LDSM_X4(r0, r1, r2, r3, addr);
                bF[2 * nt2][0]     = r0;
                bF[2 * nt2 + 1][0] = r1;
                bF[2 * nt2][1]     = r2;
                bF[2 * nt2 + 1][1] = r3;
            }
            #pragma unroll
            for (int mt = 0; mt < 2; mt++)
                #pragma unroll
                for (int nt = 0; nt < 8; nt++)
                    MMA16816(acc[mt][nt], aF[mt], bF[nt]);
        }
        s = (s == 2) ? 0 : s + 1;
        ps = (ps == 2) ? 0 : ps + 1;
    }

    // Epilogue
    const int erow = lane >> 2;
    const int ecol = (lane & 3) * 2;
    #pragma unroll
    for (int mt = 0; mt < 2; mt++) {
        #pragma unroll
        for (int nt = 0; nt < 8; nt++) {
            const long r  = row0 + warp_m + mt * 16 + erow;
            const long cc = cc0 + warp_n + nt * 8 + ecol;
            float b0 = bias ? bias[cc] : 0.0f;
            float b1 = bias ? bias[cc + 1] : 0.0f;
            float2 v0 = make_float2(acc[mt][nt][0] + b0, acc[mt][nt][1] + b1);
            float2 v1 = make_float2(acc[mt][nt][2] + b0, acc[mt][nt][3] + b1);
            *(float2*)(C + r * DD + cc)       = v0;
            *(float2*)(C + (r + 8) * DD + cc) = v1;
        }
    }
}

// ---------------------------------------------------------------------------
// Local-window attention (flash-style, fp32), optimized PV path.
// Score cols per thread: c*4+j. Output cols per thread: c*8+dd.
// Ps stored transposed: Ps_T[kcol][qrow], float4 loads in PV.
// Epilogue also emits bf16 hi/lo split of the output (feeds Wo gemm).
// SMEM: Qs[128][65] + Ks[128][65] + Vs[64][128] + Ps_T[64][64] = 115712 B
// ---------------------------------------------------------------------------
#define BQ   64
#define BKC  64
#define ATT_SMEM_BYTES ((128*65 + 128*65 + 64*128 + 64*64) * 4)

__global__ __launch_bounds__(256, 2) void attn_local_kernel(
    const float* __restrict__ Q, const float* __restrict__ K,
    const float* __restrict__ V, const int* __restrict__ amask,
    float* __restrict__ O,
    __nv_bfloat16* __restrict__ OH, __nv_bfloat16* __restrict__ OL)
{
    const int q0 = blockIdx.x * BQ;
    const int h  = blockIdx.y;
    const int b  = blockIdx.z;

    extern __shared__ float sm[];
    float* Qs  = sm;                      // [128][65]
    float* Ks  = Qs + 128 * 65;           // [128][65]
    float* Vs  = Ks + 128 * 65;           // [64][128]
    float* PsT = Vs + 64 * 128;           // [64][64]  (kcol-major)

    const int tid = threadIdx.x;
    const int r   = tid >> 4;             // 0..15 -> q rows r*4..r*4+3
    const int c   = tid & 15;

    const float* qbase = Q + ((long)(b * SS + q0)) * DD + h * HDIM;
    for (int e = tid; e < BQ * HDIM; e += 256) {
        int qi = e >> 7, d = e & 127;
        Qs[d * 65 + qi] = qbase[(long)qi * DD + d];
    }

    float m[4], l[4], o[4][8];
    #pragma unroll
    for (int i = 0; i < 4; i++) {
        m[i] = -FLT_MAX; l[i] = 0.0f;
        #pragma unroll
        for (int dd = 0; dd < 8; dd++) o[i][dd] = 0.0f;
    }

    for (int t = 0; t < 5; t++) {
        const int kb = q0 - WINDOW + t * BKC;
        if (kb < 0) continue;

        __syncthreads();

        const float* kbase = K + ((long)(b * SS + kb)) * DD + h * HDIM;
        const float* vbase = V + ((long)(b * SS + kb)) * DD + h * HDIM;
        for (int e = tid; e < BKC * HDIM; e += 256) {
            int kj = e >> 7, d = e & 127;
            Ks[d * 65 + kj]  = kbase[(long)kj * DD + d];
            Vs[kj * 128 + d] = vbase[(long)kj * DD + d];
        }
        __syncthreads();

        // S = Q @ K^T (unscaled). Thread covers rows r*4+i, cols c*4+j.
        float s[4][4];
        #pragma unroll
        for (int i = 0; i < 4; i++)
            #pragma unroll
            for (int j = 0; j < 4; j++) s[i][j] = 0.0f;

        for (int d = 0; d < HDIM; d++) {
            float qv[4], kv[4];
            #pragma unroll
            for (int i = 0; i < 4; i++) qv[i] = Qs[d * 65 + r * 4 + i];
            #pragma unroll
            for (int j = 0; j < 4; j++) kv[j] = Ks[d * 65 + c * 4 + j];
            #pragma unroll
            for (int i = 0; i < 4; i++)
                #pragma unroll
                for (int j = 0; j < 4; j++)
                    s[i][j] = fmaf(qv[i], kv[j], s[i][j]);
        }

        // Mask + online softmax
        float scl[4];
        #pragma unroll
        for (int i = 0; i < 4; i++) {
            const int qi = q0 + r * 4 + i;
            #pragma unroll
            for (int j = 0; j < 4; j++) {
                const int kj = kb + c * 4 + j;
                bool ok = (kj <= qi) && (kj > qi - WINDOW) && (amask[b * SS + kj] > 0);
                if (!ok) s[i][j] = -FLT_MAX;
            }
            float mx = fmaxf(fmaxf(s[i][0], s[i][1]), fmaxf(s[i][2], s[i][3]));
            #pragma unroll
            for (int w = 1; w <= 8; w <<= 1)
                mx = fmaxf(mx, __shfl_xor_sync(0xffffffffu, mx, w));

            float mnew = fmaxf(m[i], mx);
            scl[i] = __expf(m[i] - mnew);
            m[i] = mnew;

            float sum = 0.0f;
            #pragma unroll
            for (int j = 0; j < 4; j++) {
                float p = (s[i][j] > -1e37f) ? __expf(s[i][j] - mnew) : 0.0f;
                s[i][j] = p;
                sum += p;
            }
            #pragma unroll
            for (int w = 1; w <= 8; w <<= 1)
                sum += __shfl_xor_sync(0xffffffffu, sum, w);

            l[i] = l[i] * scl[i] + sum;
            #pragma unroll
            for (int dd = 0; dd < 8; dd++) o[i][dd] *= scl[i];
        }

        // Stage P transposed: PsT[kcol][qrow], one float4 per j
        #pragma unroll
        for (int j = 0; j < 4; j++) {
            float4 pv = make_float4(s[0][j], s[1][j], s[2][j], s[3][j]);
            *(float4*)&PsT[(c * 4 + j) * 64 + r * 4] = pv;
        }
        __syncthreads();

        // O += P @ V  (thread's cols: c*8..c*8+7)
        #pragma unroll 8
        for (int j = 0; j < BKC; j++) {
            float4 p4 = *(const float4*)&PsT[j * 64 + r * 4];
            float4 va = *(const float4*)&Vs[j * 128 + c * 8];
            float4 vb = *(const float4*)&Vs[j * 128 + c * 8 + 4];
            const float pv[4] = {p4.x, p4.y, p4.z, p4.w};
            const float vv[8] = {va.x, va.y, va.z, va.w, vb.x, vb.y, vb.z, vb.w};
            #pragma unroll
            for (int i = 0; i < 4; i++)
                #pragma unroll
                for (int dd = 0; dd < 8; dd++)
                    o[i][dd] = fmaf(pv[i], vv[dd], o[i][dd]);
        }
    }

    // Normalize + store fp32 AND bf16 hi/lo split
    #pragma unroll
    for (int i = 0; i < 4; i++) {
        const int row = q0 + r * 4 + i;
        const float inv = 1.0f / l[i];
        const long base = ((long)(b * SS + row)) * DD + h * HDIM + c * 8;
        float out[8];
        #pragma unroll
        for (int dd = 0; dd < 8; dd++) out[dd] = o[i][dd] * inv;
        *(float4*)(O + base)     = make_float4(out[0], out[1], out[2], out[3]);
        *(float4*)(O + base + 4) = make_float4(out[4], out[5], out[6], out[7]);
        #pragma unroll
        for (int p2 = 0; p2 < 4; p2++) {
            __nv_bfloat16 h0 = __float2bfloat16(out[2*p2]);
            __nv_bfloat16 h1 = __float2bfloat16(out[2*p2+1]);
            __nv_bfloat16 l0 = __float2bfloat16(out[2*p2]   - __bfloat162float(h0));
            __nv_bfloat16 l1 = __float2bfloat16(out[2*p2+1] - __bfloat162float(h1));
            *(__nv_bfloat162*)(OH + base + 2*p2) = __nv_bfloat162(h0, h1);
            *(__nv_bfloat162*)(OL + base + 2*p2) = __nv_bfloat162(l0, l1);
        }
    }
}

// ---------------------------------------------------------------------------
// Launch
// ---------------------------------------------------------------------------
extern "C" void kernel_launch(void* const* d_in, const int* in_sizes, int n_in,
                              void* d_out, int out_size)
{
    const float* hs    = (const float*)d_in[0];
    const int*   amask = (const int*)  d_in[1];
    const float* Wq    = (const float*)d_in[2];
    const float* Wk    = (const float*)d_in[3];
    const float* Wv    = (const float*)d_in[4];
    const float* Wo    = (const float*)d_in[5];
    const float* bo    = (const float*)d_in[6];
    float*       out   = (float*)d_out;

    float *qkv, *ao;
    __nv_bfloat16 *ahi, *alo, *whi, *wlo;
    cudaGetSymbolAddress((void**)&qkv, g_qkv);
    cudaGetSymbolAddress((void**)&ao,  g_ao);
    cudaGetSymbolAddress((void**)&ahi, g_ahi);
    cudaGetSymbolAddress((void**)&alo, g_alo);
    cudaGetSymbolAddress((void**)&whi, g_whi);
    cudaGetSymbolAddress((void**)&wlo, g_wlo);

    cudaFuncSetAttribute(gemm_bf16x3_kernel,
                         cudaFuncAttributeMaxDynamicSharedMemorySize, GSMEM_TOTAL);
    cudaFuncSetAttribute(attn_local_kernel,
                         cudaFuncAttributeMaxDynamicSharedMemorySize, ATT_SMEM_BYTES);

    const int n4 = MROWS * DD / 4;
    dim3 wgrid(DD / 32, DD / 32);               // (64, 64)

    // Split activations; pack + split weights for fused QKV
    split_kernel<<<(n4 + 255) / 256, 256>>>(hs, ahi, alo, n4);
    wsplitT_kernel<<<wgrid, 256>>>(Wq, whi,              wlo);
    wsplitT_kernel<<<wgrid, 256>>>(Wk, whi + (long)DD*DD, wlo + (long)DD*DD);
    wsplitT_kernel<<<wgrid, 256>>>(Wv, whi + 2L*DD*DD,    wlo + 2L*DD*DD);

    // Fused QKV GEMM: grid (48, 32) = 1536 CTAs, 2/SM
    dim3 qkvgrid(3 * DD / 128, MROWS / 128);
    gemm_bf16x3_kernel<<<qkvgrid, 256, GSMEM_TOTAL>>>(ahi, alo, whi, wlo, nullptr, qkv);

    // Prepare Wo while attention's inputs are final (stream-ordered after QKV gemm)
    wsplitT_kernel<<<wgrid, 256>>>(Wo, whi, wlo);

    // Attention (writes ao fp32 + ahi/alo bf16 split for the Wo gemm)
    dim3 attn_grid(SS / BQ, HH, BB);            // (32, 16, 2)
    attn_local_kernel<<<attn_grid, 256, ATT_SMEM_BYTES>>>(
        qkv, qkv + MD, qkv + 2 * MD, amask, ao, ahi, alo);

    // Output projection
    dim3 ogrid(DD / 128, MROWS / 128);          // (16, 32)
    gemm_bf16x3_kernel<<<ogrid, 256, GSMEM_TOTAL>>>(ahi, alo, whi, wlo, bo, out);
}